// round 16
// baseline (speedup 1.0000x reference)
#include <cuda_runtime.h>

#define BB   16
#define NN   512
#define DIN  256
#define DD   64
#define EE   32
#define MAXDIST 50

typedef unsigned long long ull;

__device__ __forceinline__ float ex2(float x) {
    float r;
    asm("ex2.approx.f32 %0, %1;" : "=f"(r) : "f"(x));
    return r;
}
__device__ __forceinline__ unsigned cvt_tf32(float x) {
    unsigned r;
    asm("cvt.rna.tf32.f32 %0, %1;" : "=r"(r) : "f"(x));
    return r;
}
__device__ __forceinline__ void mma_tf32(float& c0, float& c1, float& c2, float& c3,
                                         unsigned a0, unsigned a1, unsigned a2, unsigned a3,
                                         unsigned b0, unsigned b1) {
    asm("mma.sync.aligned.m16n8k8.row.col.f32.tf32.tf32.f32 "
        "{%0,%1,%2,%3}, {%4,%5,%6,%7}, {%8,%9}, {%0,%1,%2,%3};"
        : "+f"(c0), "+f"(c1), "+f"(c2), "+f"(c3)
        : "r"(a0), "r"(a1), "r"(a2), "r"(a3), "r"(b0), "r"(b1));
}
__device__ __forceinline__ void cpa16(unsigned dst, const float* src) {
    asm volatile("cp.async.cg.shared.global [%0], [%1], 16;" :: "r"(dst), "l"(src));
}
#define CP_COMMIT() asm volatile("cp.async.commit_group;" ::: "memory")
#define CP_WAIT2()  asm volatile("cp.async.wait_group 2;" ::: "memory")
#define CP_WAIT1()  asm volatile("cp.async.wait_group 1;" ::: "memory")
#define CP_WAIT0()  asm volatile("cp.async.wait_group 0;" ::: "memory")

__device__ float g_kT[BB*DD*NN];   // per batch: [d][n], tf32-rounded
__device__ float g_v [BB*NN*DD];   // row-major [n][d], tf32-rounded
__device__ int   g_ctr[BB];        // producer doorbell (self-resetting)
__device__ int   g_done[BB];       // consumer done count (self-resetting)

#define XS_OFF  0
#define WP_OFF  16640
#define WT_OFF  35072
#define XP_OFF  48896
#define S_OFF    0
#define KB_OFF   16640
#define VA_OFF   33536
#define VB2_OFF  42752
#define QT_OFF   51968
#define REL_OFF  56576
#define RK_OFF   56640
#define WS_OFF   57152
#define INV_OFF  57408
#define SMEM_FLOATS 57472
#define SMEM_BYTES  (SMEM_FLOATS*4)

__device__ __forceinline__ void qk_chunk(
    float* S, const unsigned* qTb, const unsigned* KBu, const float* rel, const int* rk,
    int k0, int wc, int q, int g, int r0, int r1, int ri0, int ri1,
    float& rs0, float& rs1) {
    float acc[8][4];
#pragma unroll
    for (int cb = 0; cb < 8; cb++) {
        acc[cb][0] = 0.f; acc[cb][1] = 0.f; acc[cb][2] = 0.f; acc[cb][3] = 0.f;
    }
#pragma unroll
    for (int ks = 0; ks < 8; ks++) {
        unsigned a0 = qTb[(ks*8 + q)*72 + r0];
        unsigned a1 = qTb[(ks*8 + q)*72 + r1];
        unsigned a2 = qTb[(ks*8 + q + 4)*72 + r0];
        unsigned a3 = qTb[(ks*8 + q + 4)*72 + r1];
#pragma unroll
        for (int cb = 0; cb < 8; cb++) {
            int key0 = wc*64 + cb*8;
            unsigned b0 = KBu[(ks*8 + q)*264 + key0 + g];
            unsigned b1 = KBu[(ks*8 + q + 4)*264 + key0 + g];
            mma_tf32(acc[cb][0], acc[cb][1], acc[cb][2], acc[cb][3],
                     a0, a1, a2, a3, b0, b1);
        }
    }
#pragma unroll
    for (int cb = 0; cb < 8; cb++) {
        int kloc = wc*64 + cb*8 + 2*q;
        int ka = rk[k0 + kloc], kb = rk[k0 + kloc + 1];
        int d00 = ri0 - ka; d00 = d00 < 0 ? -d00 : d00; if (d00 > MAXDIST) d00 = MAXDIST;
        int d01 = ri0 - kb; d01 = d01 < 0 ? -d01 : d01; if (d01 > MAXDIST) d01 = MAXDIST;
        int d10 = ri1 - ka; d10 = d10 < 0 ? -d10 : d10; if (d10 > MAXDIST) d10 = MAXDIST;
        int d11 = ri1 - kb; d11 = d11 < 0 ? -d11 : d11; if (d11 > MAXDIST) d11 = MAXDIST;
        float f00 = __uint_as_float(cvt_tf32(ex2(acc[cb][0] * rel[d00])));
        float f01 = __uint_as_float(cvt_tf32(ex2(acc[cb][1] * rel[d01])));
        float f10 = __uint_as_float(cvt_tf32(ex2(acc[cb][2] * rel[d10])));
        float f11 = __uint_as_float(cvt_tf32(ex2(acc[cb][3] * rel[d11])));
        *(float2*)&S[r0*260 + kloc] = make_float2(f00, f01);
        *(float2*)&S[r1*260 + kloc] = make_float2(f10, f11);
        rs0 += f00 + f01;
        rs1 += f10 + f11;
    }
}

__device__ __forceinline__ void pv_half(
    const unsigned* Sb, const unsigned* VBu,
    int h, int wc, int q, int g, int r0, int r1, float (&accpv)[2][4]) {
#pragma unroll
    for (int ks = 0; ks < 16; ks++) {
        int kk = h*128 + ks*8;
        unsigned a0 = Sb[r0*260 + kk + q];
        unsigned a1 = Sb[r1*260 + kk + q];
        unsigned a2 = Sb[r0*260 + kk + q + 4];
        unsigned a3 = Sb[r1*260 + kk + q + 4];
#pragma unroll
        for (int cb = 0; cb < 2; cb++) {
            int d0 = wc*16 + cb*8;
            unsigned b0 = VBu[(ks*8 + q)*72 + d0 + g];
            unsigned b1 = VBu[(ks*8 + q + 4)*72 + d0 + g];
            mma_tf32(accpv[cb][0], accpv[cb][1], accpv[cb][2], accpv[cb][3],
                     a0, a1, a2, a3, b0, b1);
        }
    }
}

__global__ __launch_bounds__(512) void fused_kernel(
    const float* __restrict__ x, const int* __restrict__ ranks,
    const float* __restrict__ Wp, const float* __restrict__ bp,
    const float* __restrict__ Wq, const float* __restrict__ bq,
    const float* __restrict__ Wk, const float* __restrict__ bk,
    const float* __restrict__ Wv, const float* __restrict__ bv,
    const float* __restrict__ Eemb, const float* __restrict__ Wr1,
    const float* __restrict__ br1,  const float* __restrict__ Wr2,
    const float* __restrict__ Wf1, const float* __restrict__ bf1,
    const float* __restrict__ Wf2, const float* __restrict__ bf2,
    const float* __restrict__ ln_g, const float* __restrict__ ln_b,
    const float* __restrict__ Ws1, const float* __restrict__ bs1,
    const float* __restrict__ Ws2, const float* __restrict__ bs2,
    float* __restrict__ out) {
    extern __shared__ float sm[];
    const int tid = threadIdx.x;
    const int wp = tid >> 5, lane = tid & 31;
    const int g = lane >> 2, q = lane & 3;
    const int rb = wp >> 2, wc = wp & 3;
    const int r0 = rb*16 + g, r1 = r0 + 8;
    const int blk = blockIdx.x;
    const int b = blk >> 3;
    const int row0 = blk * 64;
    const int n0 = row0 & 511;
    const int q0 = n0;
    const int base = b * NN;
    const int bT = b * DD * NN;

    const unsigned sb = (unsigned)__cvta_generic_to_shared(sm);
    const unsigned kbA = sb + KB_OFF*4;
    const unsigned vaA = sb + VA_OFF*4;
    const unsigned vbA = sb + VB2_OFF*4;

    // ================= QKV PHASE =================
    {
        float* XS = sm + XS_OFF;
        float* WP = sm + WP_OFF;
        float* WT = sm + WT_OFF;
        unsigned* XSu = (unsigned*)XS;
        unsigned* WPu = (unsigned*)WP;
        unsigned* WTu = (unsigned*)WT;
        unsigned* XPu = (unsigned*)(sm + XP_OFF);
        float* rel = sm + REL_OFF;
        int*   rk  = (int*)(sm + RK_OFF);

#pragma unroll
        for (int j = 0; j < 8; j++) {
            int idx = tid + j*512;
            int row = idx >> 6, f = idx & 63;
            cpa16(sb + (unsigned)((XS_OFF + row*260 + f*4)*4), &x[(row0 + row)*DIN + f*4]);
        }
        CP_COMMIT();
#pragma unroll
        for (int j = 0; j < 8; j++) {
            int idx = tid + j*512;
            int row = idx >> 4, f = idx & 15;
            cpa16(sb + (unsigned)((WP_OFF + row*72 + f*4)*4), &Wp[row*DD + f*4]);
        }
        CP_COMMIT();
#pragma unroll
        for (int j = 0; j < 6; j++) {
            int idx = tid + j*512;
            int t = idx >> 10, rem = idx & 1023;
            int row = rem >> 4, f = rem & 15;
            const float* src = (t == 0) ? Wk : (t == 1) ? Wv : Wq;
            cpa16(sb + (unsigned)((WT_OFF + t*4608 + row*72 + f*4)*4), &src[row*DD + f*4]);
        }
        CP_COMMIT();

        if (tid <= MAXDIST) {
            float e[EE];
#pragma unroll
            for (int c = 0; c < EE; c++) e[c] = Eemb[tid*EE + c];
            float w = 0.f;
#pragma unroll
            for (int j = 0; j < 16; j++) {
                float h = br1[j];
#pragma unroll
                for (int c = 0; c < EE; c++) h = fmaf(e[c], Wr1[c*16 + j], h);
                h = fmaxf(h, 0.f);
                w = fmaf(h, Wr2[j], w);
            }
            rel[tid] = 0.18033688011112042f / (1.f + __expf(-w));
        }
        if (tid < NN) rk[tid] = ranks[base + tid];

        CP_WAIT1(); __syncthreads();          // x + Wp ready

        // pre-convert XS + WP to tf32 in place
        for (int idx = tid; idx < 16640; idx += 512) XSu[idx] = cvt_tf32(XS[idx]);
        for (int idx = tid; idx < 18432; idx += 512) WPu[idx] = cvt_tf32(WP[idx]);
        __syncthreads();

        // Phase A: xp = x @ Wp
        float acc[2][4];
#pragma unroll
        for (int cb = 0; cb < 2; cb++) {
            acc[cb][0] = 0.f; acc[cb][1] = 0.f; acc[cb][2] = 0.f; acc[cb][3] = 0.f;
        }
#pragma unroll 4
        for (int ks = 0; ks < 32; ks++) {
            unsigned a0 = XSu[r0*260 + ks*8 + q];
            unsigned a1 = XSu[r1*260 + ks*8 + q];
            unsigned a2 = XSu[r0*260 + ks*8 + q + 4];
            unsigned a3 = XSu[r1*260 + ks*8 + q + 4];
#pragma unroll
            for (int cb = 0; cb < 2; cb++) {
                int nc = wc*16 + cb*8;
                unsigned b0 = WPu[(ks*8 + q)*72 + nc + g];
                unsigned b1 = WPu[(ks*8 + q + 4)*72 + nc + g];
                mma_tf32(acc[cb][0], acc[cb][1], acc[cb][2], acc[cb][3],
                         a0, a1, a2, a3, b0, b1);
            }
        }
        CP_WAIT0();                           // WT arrived (untouched by Phase A)
        // XP epilogue (tf32) + WT convert in the SAME barrier interval
#pragma unroll
        for (int cb = 0; cb < 2; cb++) {
            int c = wc*16 + cb*8 + 2*q;
            float bp0 = bp[c], bp1 = bp[c + 1];
            XPu[r0*68 + c]     = cvt_tf32(acc[cb][0] + bp0);
            XPu[r0*68 + c + 1] = cvt_tf32(acc[cb][1] + bp1);
            XPu[r1*68 + c]     = cvt_tf32(acc[cb][2] + bp0);
            XPu[r1*68 + c + 1] = cvt_tf32(acc[cb][3] + bp1);
        }
        for (int idx = tid; idx < 13824; idx += 512) WTu[idx] = cvt_tf32(WT[idx]);
        __syncthreads();                      // XP + WT(tf32) visible

        // Phase B: k then v (to global), signal
#pragma unroll
        for (int t = 0; t < 2; t++) {
            const unsigned* W = WTu + t*4608;
            const float* bs = (t == 0) ? bk : bv;
            float o[2][4];
#pragma unroll
            for (int cb = 0; cb < 2; cb++) {
                o[cb][0] = 0.f; o[cb][1] = 0.f; o[cb][2] = 0.f; o[cb][3] = 0.f;
            }
#pragma unroll
            for (int ks = 0; ks < 8; ks++) {
                unsigned a0 = XPu[r0*68 + ks*8 + q];
                unsigned a1 = XPu[r1*68 + ks*8 + q];
                unsigned a2 = XPu[r0*68 + ks*8 + q + 4];
                unsigned a3 = XPu[r1*68 + ks*8 + q + 4];
#pragma unroll
                for (int cb = 0; cb < 2; cb++) {
                    int nc = wc*16 + cb*8;
                    unsigned b0 = W[(ks*8 + q)*72 + nc + g];
                    unsigned b1 = W[(ks*8 + q + 4)*72 + nc + g];
                    mma_tf32(o[cb][0], o[cb][1], o[cb][2], o[cb][3],
                             a0, a1, a2, a3, b0, b1);
                }
            }
            if (t == 1) {
#pragma unroll
                for (int cb = 0; cb < 2; cb++) {
                    int c = wc*16 + cb*8 + 2*q;
                    float v0 = __uint_as_float(cvt_tf32(o[cb][0] + bs[c]));
                    float v1 = __uint_as_float(cvt_tf32(o[cb][1] + bs[c + 1]));
                    float v2 = __uint_as_float(cvt_tf32(o[cb][2] + bs[c]));
                    float v3 = __uint_as_float(cvt_tf32(o[cb][3] + bs[c + 1]));
                    *(float2*)&g_v[(row0 + r0)*DD + c] = make_float2(v0, v1);
                    *(float2*)&g_v[(row0 + r1)*DD + c] = make_float2(v2, v3);
                }
            } else {
#pragma unroll
                for (int cb = 0; cb < 2; cb++) {
                    int c = wc*16 + cb*8 + 2*q;
                    g_kT[bT + c*NN + n0 + r0]       = __uint_as_float(cvt_tf32(o[cb][0] + bs[c]));
                    g_kT[bT + (c + 1)*NN + n0 + r0] = __uint_as_float(cvt_tf32(o[cb][1] + bs[c + 1]));
                    g_kT[bT + c*NN + n0 + r1]       = __uint_as_float(cvt_tf32(o[cb][2] + bs[c]));
                    g_kT[bT + (c + 1)*NN + n0 + r1] = __uint_as_float(cvt_tf32(o[cb][3] + bs[c + 1]));
                }
            }
        }
        __syncthreads();
        if (tid == 0) {
            __threadfence();
            atomicAdd(&g_ctr[b], 1);
        }

        // ---- doorbell wait ----
        if (tid == 0) {
            volatile int* c = &g_ctr[b];
            while (*c < 8) {}
            __threadfence();
        }
        __syncthreads();

        // issue K0 — hidden behind local q GEMM
#pragma unroll
        for (int j = 0; j < 8; j++) {
            int idx = tid + j*512;
            int d = idx >> 6, f = idx & 63;
            cpa16(kbA + (unsigned)((d*264 + f*4)*4), &g_kT[bT + d*NN + f*4]);
        }
        CP_COMMIT();                          // grp1: K0

        // q (local)
        {
            const unsigned* W = WTu + 2*4608;
            float o[2][4];
#pragma unroll
            for (int cb = 0; cb < 2; cb++) {
                o[cb][0] = 0.f; o[cb][1] = 0.f; o[cb][2] = 0.f; o[cb][3] = 0.f;
            }
#pragma unroll
            for (int ks = 0; ks < 8; ks++) {
                unsigned a0 = XPu[r0*68 + ks*8 + q];
                unsigned a1 = XPu[r1*68 + ks*8 + q];
                unsigned a2 = XPu[r0*68 + ks*8 + q + 4];
                unsigned a3 = XPu[r1*68 + ks*8 + q + 4];
#pragma unroll
                for (int cb = 0; cb < 2; cb++) {
                    int nc = wc*16 + cb*8;
                    unsigned b0 = W[(ks*8 + q)*72 + nc + g];
                    unsigned b1 = W[(ks*8 + q + 4)*72 + nc + g];
                    mma_tf32(o[cb][0], o[cb][1], o[cb][2], o[cb][3],
                             a0, a1, a2, a3, b0, b1);
                }
            }
            __syncthreads();                  // XP/WT reads done
            unsigned* qTu = (unsigned*)(sm + QT_OFF);
#pragma unroll
            for (int cb = 0; cb < 2; cb++) {
                int c = wc*16 + cb*8 + 2*q;
                qTu[c*72 + r0]       = cvt_tf32(o[cb][0] + bq[c]);
                qTu[(c + 1)*72 + r0] = cvt_tf32(o[cb][1] + bq[c + 1]);
                qTu[c*72 + r1]       = cvt_tf32(o[cb][2] + bq[c]);
                qTu[(c + 1)*72 + r1] = cvt_tf32(o[cb][3] + bq[c + 1]);
            }
        }
        // issue Va, Vb — XP dead now
#pragma unroll
        for (int j = 0; j < 4; j++) {
            int idx = tid + j*512;
            int key = idx >> 4, f = idx & 15;
            cpa16(vaA + (unsigned)((key*72 + f*4)*4), &g_v[(base + key)*DD + f*4]);
        }
        CP_COMMIT();                          // grp2: Va
#pragma unroll
        for (int j = 0; j < 4; j++) {
            int idx = tid + j*512;
            int key = idx >> 4, f = idx & 15;
            cpa16(vbA + (unsigned)((key*72 + f*4)*4), &g_v[(base + 128 + key)*DD + f*4]);
        }
        CP_COMMIT();                          // grp3: Vb
    }

    // ================= ATTN PHASE =================
    {
        float* S    = sm + S_OFF;
        float* KB   = sm + KB_OFF;
        float* VAf  = sm + VA_OFF;
        float* VBf  = sm + VB2_OFF;
        float* qTf  = sm + QT_OFF;
        float* rel  = sm + REL_OFF;
        int*   rk   = (int*)(sm + RK_OFF);
        float* wsum = sm + WS_OFF;
        float* invs = sm + INV_OFF;
        float* wsq  = sm + 11264;
        const unsigned* qTb = (const unsigned*)qTf;
        const unsigned* Sb  = (const unsigned*)S;
        const unsigned* KBu = (const unsigned*)KB;
        const unsigned* VAu = (const unsigned*)VAf;
        const unsigned* VBu = (const unsigned*)VBf;

        float rs0 = 0.f, rs1 = 0.f;
        float accpv[2][4];
#pragma unroll
        for (int c = 0; c < 2; c++) {
            accpv[c][0] = 0.f; accpv[c][1] = 0.f; accpv[c][2] = 0.f; accpv[c][3] = 0.f;
        }

        CP_WAIT2(); __syncthreads();                           // K0 ready, qT visible
        const int ri0 = rk[q0 + r0], ri1 = rk[q0 + r1];

        qk_chunk(S, qTb, KBu, rel, rk, 0, wc, q, g, r0, r1, ri0, ri1, rs0, rs1);
        __syncthreads();                                       // S0 ready, KB free

#pragma unroll
        for (int j = 0; j < 8; j++) {
            int idx = tid + j*512;
            int d = idx >> 6, f = idx & 63;
            cpa16(kbA + (unsigned)((d*264 + f*4)*4), &g_kT[bT + d*NN + 256 + f*4]);
        }
        CP_COMMIT();                                          // grp4: K1

        CP_WAIT2(); __syncthreads();                           // Va ready
        pv_half(Sb, VAu, 0, wc, q, g, r0, r1, accpv);
        CP_WAIT1(); __syncthreads();                           // Vb ready, VA free
#pragma unroll
        for (int j = 0; j < 4; j++) {
            int idx = tid + j*512;
            int key = idx >> 4, f = idx & 15;
            cpa16(vaA + (unsigned)((key*72 + f*4)*4), &g_v[(base + 256 + key)*DD + f*4]);
        }
        CP_COMMIT();                                          // grp5: Va2
        pv_half(Sb, VBu, 1, wc, q, g, r0, r1, accpv);
        __syncthreads();                                       // VB free, S free
#pragma unroll
        for (int j = 0; j < 4; j++) {
            int idx = tid + j*512;
            int key = idx >> 4, f = idx & 15;
            cpa16(vbA + (unsigned)((key*72 + f*4)*4), &g_v[(base + 384 + key)*DD + f*4]);
        }
        CP_COMMIT();                                          // grp6: Vb2
        CP_WAIT2(); __syncthreads();                           // K1 ready

        qk_chunk(S, qTb, KBu, rel, rk, 256, wc, q, g, r0, r1, ri0, ri1, rs0, rs1);
        {
            rs0 += __shfl_xor_sync(0xffffffffu, rs0, 1);
            rs0 += __shfl_xor_sync(0xffffffffu, rs0, 2);
            rs1 += __shfl_xor_sync(0xffffffffu, rs1, 1);
            rs1 += __shfl_xor_sync(0xffffffffu, rs1, 2);
            if (q == 0) {
                wsum[wc*64 + r0] = rs0;
                wsum[wc*64 + r1] = rs1;
            }
        }
        __syncthreads();
        if (tid < 64)
            invs[tid] = 1.f / (wsum[tid] + wsum[64 + tid] + wsum[128 + tid] + wsum[192 + tid]);
#pragma unroll
        for (int j = 0; j < 8; j++) {
            int idx = tid + j*512;
            int k = idx >> 5, f = idx & 31;
            cpa16(kbA + (unsigned)((k*132 + f*4)*4), &Wf1[k*128 + f*4]);
        }
        CP_COMMIT();                                          // grp7: w1

        CP_WAIT2(); __syncthreads();                           // Va2 ready (+invs)
        pv_half(Sb, VAu, 0, wc, q, g, r0, r1, accpv);
        CP_WAIT1(); __syncthreads();                           // Vb2 ready
        pv_half(Sb, VBu, 1, wc, q, g, r0, r1, accpv);
        CP_WAIT0();
        __syncthreads();                                       // w1 ready, PV done

        // issue Wf2 -> VA [128][72], ws1/ws2 -> VB (overlap PV epi + FFN1)
#pragma unroll
        for (int j = 0; j < 4; j++) {
            int idx = tid + j*512;
            int k = idx >> 4, f = idx & 15;
            cpa16(vaA + (unsigned)((k*72 + f*4)*4), &Wf2[k*64 + f*4]);
        }
        cpa16(vbA + (unsigned)(tid*16), &Ws1[tid*4]);
        if (tid < 8) cpa16(vbA + (unsigned)((2048 + tid*4)*4), &Ws2[tid*4]);
        CP_COMMIT();                                          // grp8

        // PV epilogue: 1/sum, aoT(tf32) -> qTf
        {
            unsigned* aoT = (unsigned*)qTf;
            float iv0 = invs[r0], iv1 = invs[r1];
#pragma unroll
            for (int cb = 0; cb < 2; cb++) {
                int dc = wc*16 + cb*8 + 2*q;
                aoT[dc*68 + r0]       = cvt_tf32(accpv[cb][0] * iv0);
                aoT[(dc + 1)*68 + r0] = cvt_tf32(accpv[cb][1] * iv0);
                aoT[dc*68 + r1]       = cvt_tf32(accpv[cb][2] * iv1);
                aoT[(dc + 1)*68 + r1] = cvt_tf32(accpv[cb][3] * iv1);
            }
        }
        __syncthreads();

        // FFN1: tf32 mma, M64 N128 K64
        {
            const unsigned* aoT = (const unsigned*)qTf;
            float f1[4][4];
#pragma unroll
            for (int cb = 0; cb < 4; cb++) {
                f1[cb][0] = 0.f; f1[cb][1] = 0.f; f1[cb][2] = 0.f; f1[cb][3] = 0.f;
            }
#pragma unroll
            for (int ks = 0; ks < 8; ks++) {
                unsigned a0 = aoT[(ks*8 + q)*68 + r0];
                unsigned a1 = aoT[(ks*8 + q)*68 + r1];
                unsigned a2 = aoT[(ks*8 + q + 4)*68 + r0];
                unsigned a3 = aoT[(ks*8 + q + 4)*68 + r1];
#pragma unroll
                for (int cb = 0; cb < 4; cb++) {
                    int nc = wc*32 + cb*8;
                    unsigned b0 = cvt_tf32(KB[(ks*8 + q)*132 + nc + g]);
                    unsigned b1 = cvt_tf32(KB[(ks*8 + q + 4)*132 + nc + g]);
                    mma_tf32(f1[cb][0], f1[cb][1], f1[cb][2], f1[cb][3],
                             a0, a1, a2, a3, b0, b1);
                }
            }
            unsigned* h1T = (unsigned*)S;
#pragma unroll
            for (int cb = 0; cb < 4; cb++) {
                int c = wc*32 + cb*8 + 2*q;
                float bc0 = bf1[c], bc1 = bf1[c + 1];
                h1T[c*68 + r0]       = cvt_tf32(fmaxf(f1[cb][0] + bc0, 0.f));
                h1T[(c + 1)*68 + r0] = cvt_tf32(fmaxf(f1[cb][1] + bc1, 0.f));
                h1T[c*68 + r1]       = cvt_tf32(fmaxf(f1[cb][2] + bc0, 0.f));
                h1T[(c + 1)*68 + r1] = cvt_tf32(fmaxf(f1[cb][3] + bc1, 0.f));
            }
        }
        CP_WAIT0();                                            // Wf2 + ws arrived
        __syncthreads();                                       // h1T + VA/VB visible

        // FFN2 + LayerNorm, M64 N64 K128 (B from VA stride 72)
        {
            const unsigned* h1T = (const unsigned*)S;
            float f2[2][4];
            f2[0][0] = f2[0][1] = f2[0][2] = f2[0][3] = 0.f;
            f2[1][0] = f2[1][1] = f2[1][2] = f2[1][3] = 0.f;
#pragma unroll
            for (int ks = 0; ks < 16; ks++) {
                unsigned a0 = h1T[(ks*8 + q)*68 + r0];
                unsigned a1 = h1T[(ks*8 + q)*68 + r1];
                unsigned a2 = h1T[(ks*8 + q + 4)*68 + r0];
                unsigned a3 = h1T[(ks*8 + q + 4)*68 + r1];
#pragma unroll
                for (int cb = 0; cb < 2; cb++) {
                    int nc = wc*16 + cb*8;
                    unsigned b0 = cvt_tf32(VAf[(ks*8 + q)*72 + nc + g]);
                    unsigned b1 = cvt_tf32(VAf[(ks*8 + q + 4)*72 + nc + g]);
                    mma_tf32(f2[cb][0], f2[cb][1], f2[cb][2], f2[cb][3],
                             a0, a1, a2, a3, b0, b1);
                }
            }
            float e[2][4];
            float s0 = 0.f, q0s = 0.f, s1v = 0.f, q1s = 0.f;
#pragma unroll
            for (int cb = 0; cb < 2; cb++) {
                int c = wc*16 + cb*8 + 2*q;
                e[cb][0] = f2[cb][0] + bf2[c];
                e[cb][1] = f2[cb][1] + bf2[c + 1];
                e[cb][2] = f2[cb][2] + bf2[c];
                e[cb][3] = f2[cb][3] + bf2[c + 1];
                s0  += e[cb][0] + e[cb][1];
                q0s += e[cb][0]*e[cb][0] + e[cb][1]*e[cb][1];
                s1v += e[cb][2] + e[cb][3];
                q1s += e[cb][2]*e[cb][2] + e[cb][3]*e[cb][3];
            }
#pragma unroll
            for (int o = 1; o <= 2; o <<= 1) {
                s0  += __shfl_xor_sync(0xffffffffu, s0,  o);
                q0s += __shfl_xor_sync(0xffffffffu, q0s, o);
                s1v += __shfl_xor_sync(0xffffffffu, s1v, o);
                q1s += __shfl_xor_sync(0xffffffffu, q1s, o);
            }
            if (q == 0) {
                wsum[wc*64 + r0] = s0;  wsq[wc*64 + r0] = q0s;
                wsum[wc*64 + r1] = s1v; wsq[wc*64 + r1] = q1s;
            }
            __syncthreads();
            float S0 = wsum[r0] + wsum[64 + r0] + wsum[128 + r0] + wsum[192 + r0];
            float Q0 = wsq[r0]  + wsq[64 + r0]  + wsq[128 + r0]  + wsq[192 + r0];
            float S1 = wsum[r1] + wsum[64 + r1] + wsum[128 + r1] + wsum[192 + r1];
            float Q1 = wsq[r1]  + wsq[64 + r1]  + wsq[128 + r1]  + wsq[192 + r1];
            float mu0 = S0 * (1.f/64.f), mu1 = S1 * (1.f/64.f);
            float in0 = rsqrtf(Q0 * (1.f/64.f) - mu0*mu0 + 1e-5f);
            float in1 = rsqrtf(Q1 * (1.f/64.f) - mu1*mu1 + 1e-5f);
#pragma unroll
            for (int cb = 0; cb < 2; cb++) {
                int c = wc*16 + cb*8 + 2*q;
                float g0v = ln_g[c], g1v = ln_g[c + 1];
                float be0 = ln_b[c], be1 = ln_b[c + 1];
                qTf[c*68 + r0]       = (e[cb][0] - mu0)*in0*g0v + be0;
                qTf[(c + 1)*68 + r0] = (e[cb][1] - mu0)*in0*g1v + be1;
                qTf[c*68 + r1]       = (e[cb][2] - mu1)*in1*g0v + be0;
                qTf[(c + 1)*68 + r1] = (e[cb][3] - mu1)*in1*g1v + be1;
            }
        }
        __syncthreads();

        // head: all 512 threads, 2 rows per 16-lane slot
        {
            const int slot = tid >> 4;
            const int tx4 = tid & 15;
            float s1[2][2];
            s1[0][0] = s1[0][1] = s1[1][0] = s1[1][1] = 0.f;
#pragma unroll 4
            for (int kk = 0; kk < 64; kk++) {
                float2 a = *(const float2*)&qTf[kk*68 + slot*2];
                float w0 = VBf[kk*32 + tx4*2], w1b = VBf[kk*32 + tx4*2 + 1];
                s1[0][0] = fmaf(a.x, w0, s1[0][0]); s1[0][1] = fmaf(a.x, w1b, s1[0][1]);
                s1[1][0] = fmaf(a.y, w0, s1[1][0]); s1[1][1] = fmaf(a.y, w1b, s1[1][1]);
            }
            float w2a = VBf[2048 + tx4*2], w2b = VBf[2048 + tx4*2 + 1];
            float ba = bs1[tx4*2], bb = bs1[tx4*2 + 1];
            float bs2v = bs2[0];
#pragma unroll
            for (int r = 0; r < 2; r++) {
                float pa = fmaxf(s1[r][0] + ba, 0.f);
                float pb = fmaxf(s1[r][1] + bb, 0.f);
                float p = pa*w2a + pb*w2b;
#pragma unroll
                for (int o = 8; o >= 1; o >>= 1) p += __shfl_xor_sync(0xffffffffu, p, o, 16);
                if (tx4 == 0) {
                    float z = p + bs2v;
                    out[base + q0 + slot*2 + r] = 1.f / (1.f + __expf(-z));
                }
            }
        }
    }

    // ---- self-resetting counters for graph replay ----
    __syncthreads();
    if (tid == 0) {
        int d = atomicAdd(&g_done[b], 1);
        if (d == 7) {
            g_ctr[b] = 0;
            g_done[b] = 0;
            __threadfence();
        }
    }
}

// ============================================================
extern "C" void kernel_launch(void* const* d_in, const int* in_sizes, int n_in,
                              void* d_out, int out_size) {
    const float* x     = (const float*)d_in[0];
    const int*   ranks = (const int*)  d_in[1];
    const float* Wp    = (const float*)d_in[2];
    const float* bp    = (const float*)d_in[3];
    const float* Wq    = (const float*)d_in[4];
    const float* bq    = (const float*)d_in[5];
    const float* Wk    = (const float*)d_in[6];
    const float* bk    = (const float*)d_in[7];
    const float* Wv    = (const float*)d_in[8];
    const float* bv    = (const float*)d_in[9];
    const float* Eemb  = (const float*)d_in[10];
    const float* Wr1   = (const float*)d_in[11];
    const float* br1   = (const float*)d_in[12];
    const float* Wr2   = (const float*)d_in[13];
    const float* Wf1   = (const float*)d_in[14];
    const float* bf1   = (const float*)d_in[15];
    const float* Wf2   = (const float*)d_in[16];
    const float* bf2   = (const float*)d_in[17];
    const float* ln_g  = (const float*)d_in[18];
    const float* ln_b  = (const float*)d_in[19];
    const float* Ws1   = (const float*)d_in[20];
    const float* bs1   = (const float*)d_in[21];
    const float* Ws2   = (const float*)d_in[22];
    const float* bs2   = (const float*)d_in[23];
    float* out = (float*)d_out;

    cudaFuncSetAttribute(fused_kernel, cudaFuncAttributeMaxDynamicSharedMemorySize, SMEM_BYTES);

    fused_kernel<<<BB*NN/64, 512, SMEM_BYTES>>>(
        x, ranks, Wp, bp, Wq, bq, Wk, bk, Wv, bv,
        Eemb, Wr1, br1, Wr2, Wf1, bf1, Wf2, bf2,
        ln_g, ln_b, Ws1, bs1, Ws2, bs2, out);
}